// round 4
// baseline (speedup 1.0000x reference)
#include <cuda_runtime.h>
#include <math.h>

typedef unsigned long long ull;

#define NN 50000
#define RPAD 50176
#define EE 800000
#define KH 20
#define SBLK 196          // ceil(NN/256)

// ---------------- scratch (device globals; zero-init at module load) ---------
__device__ float g_XL[(size_t)RPAD * 224];  // layer input/activations
__device__ float g_A0[(size_t)RPAD * 224];  // hop ping
__device__ float g_A1[(size_t)RPAD * 224];  // hop pong
__device__ float g_AC[(size_t)RPAD * 224];  // accumulator
__device__ float  g_deg[NN];
__device__ float  g_dis[NN];
__device__ int    g_cnt[NN];
__device__ int    g_rowptr[NN + 1];
__device__ int    g_cursor[NN];
__device__ int    g_bsum[256];
__device__ int    g_boff[256];
__device__ float2 g_cv[EE];

// ---------------- f32x2 helpers ----------------
__device__ __forceinline__ ull fma2(ull a, ull b, ull c) {
    ull d;
    asm("fma.rn.f32x2 %0, %1, %2, %3;" : "=l"(d) : "l"(a), "l"(b), "l"(c));
    return d;
}
__device__ __forceinline__ ull dup2(float v) {
    ull d;
    asm("mov.b64 %0, {%1, %1};" : "=l"(d) : "f"(v));
    return d;
}
__device__ __forceinline__ float2 unpack2(ull v) {
    float2 r;
    asm("mov.b64 {%0, %1}, %2;" : "=f"(r.x), "=f"(r.y) : "l"(v));
    return r;
}

// ---------------- CSR build ----------------
__global__ void k_zero_nodes() {
    int i = blockIdx.x * blockDim.x + threadIdx.x;
    if (i < NN) { g_deg[i] = 0.f; g_cnt[i] = 0; }
}
__global__ void k_degcnt(const int* __restrict__ ei, const float* __restrict__ ew) {
    int e = blockIdx.x * blockDim.x + threadIdx.x;
    if (e < EE) {
        int d = ei[EE + e];
        atomicAdd(&g_deg[d], ew[e]);
        atomicAdd(&g_cnt[d], 1);
    }
}
__global__ void k_dis() {
    int i = blockIdx.x * blockDim.x + threadIdx.x;
    if (i < NN) {
        float d = g_deg[i];
        g_dis[i] = (d > 0.f) ? rsqrtf(d) : 0.f;
    }
}
__global__ void k_bsum() {
    __shared__ int sh[256];
    int t = threadIdx.x, i = blockIdx.x * 256 + t;
    sh[t] = (i < NN) ? g_cnt[i] : 0;
    __syncthreads();
    for (int o = 128; o; o >>= 1) {
        if (t < o) sh[t] += sh[t + o];
        __syncthreads();
    }
    if (!t) g_bsum[blockIdx.x] = sh[0];
}
__global__ void k_bscan() {
    __shared__ int sh[256];
    int t = threadIdx.x;
    int v = (t < SBLK) ? g_bsum[t] : 0;
    sh[t] = v;
    __syncthreads();
    for (int o = 1; o < 256; o <<= 1) {
        int u = (t >= o) ? sh[t - o] : 0;
        __syncthreads();
        sh[t] += u;
        __syncthreads();
    }
    if (t < SBLK) g_boff[t] = sh[t] - v;
}
__global__ void k_wptr() {
    __shared__ int sh[256];
    int t = threadIdx.x, i = blockIdx.x * 256 + t;
    int v = (i < NN) ? g_cnt[i] : 0;
    sh[t] = v;
    __syncthreads();
    for (int o = 1; o < 256; o <<= 1) {
        int u = (t >= o) ? sh[t - o] : 0;
        __syncthreads();
        sh[t] += u;
        __syncthreads();
    }
    int excl = sh[t] - v + g_boff[blockIdx.x];
    if (i < NN) {
        g_rowptr[i] = excl;
        g_cursor[i] = excl;
        if (i == NN - 1) g_rowptr[NN] = excl + v;
    }
}
__global__ void k_scatter(const int* __restrict__ ei, const float* __restrict__ ew) {
    int e = blockIdx.x * blockDim.x + threadIdx.x;
    if (e < EE) {
        int s = ei[e];
        int d = ei[EE + e];
        int p = atomicAdd(&g_cursor[d], 1);
        float2 cv;
        cv.x = __int_as_float(s);
        cv.y = g_dis[s] * ew[e] * g_dis[d];
        g_cv[p] = cv;
    }
}

// ---------------- vector propagation: warp/node, CH 32-wide chunks -----------
template <int CH>
__global__ void __launch_bounds__(256) k_prop(const float* __restrict__ hin,
                                              float* __restrict__ hout) {
    int w = (blockIdx.x * 256 + threadIdx.x) >> 5;
    if (w >= NN) return;
    int lane = threadIdx.x & 31;
    int beg = g_rowptr[w], end = g_rowptr[w + 1];
    const int S = CH * 32;
    float acc[CH];
#pragma unroll
    for (int t = 0; t < CH; ++t) acc[t] = 0.f;
    int p = beg;
    for (; p + 2 <= end; p += 2) {
        float2 cv0 = __ldg(&g_cv[p]);
        float2 cv1 = __ldg(&g_cv[p + 1]);
        const float* r0 = hin + (size_t)__float_as_int(cv0.x) * S + lane;
        const float* r1 = hin + (size_t)__float_as_int(cv1.x) * S + lane;
#pragma unroll
        for (int t = 0; t < CH; ++t) acc[t] += cv0.y * __ldg(r0 + 32 * t);
#pragma unroll
        for (int t = 0; t < CH; ++t) acc[t] += cv1.y * __ldg(r1 + 32 * t);
    }
    if (p < end) {
        float2 cv = __ldg(&g_cv[p]);
        const float* r = hin + (size_t)__float_as_int(cv.x) * S + lane;
#pragma unroll
        for (int t = 0; t < CH; ++t) acc[t] += cv.y * __ldg(r + 32 * t);
    }
    float* o = hout + (size_t)w * S + lane;
#pragma unroll
    for (int t = 0; t < CH; ++t) o[32 * t] = acc[t];
}

// ---------------- GEMM with packed f32x2 FMA ----------------
// MODE 0: D = P                      (store)
// MODE 1: D += P                     (accumulate)
// MODE 2: D2 = relu(D + P + bias)    (final: read ACC, fused bias+relu to D2)
#define BM 128
#define BN 64
#define BK 16
template <int MODE>
__global__ void __launch_bounds__(256) k_gemm(const float* __restrict__ H, int sH, int Cin,
                                              const float* __restrict__ B, int Cout,
                                              float* __restrict__ D, int sD,
                                              const float* __restrict__ bias,
                                              float* __restrict__ D2, int sD2) {
    __shared__ float As[BK][BM + 8];
    __shared__ ull   Bs2[BK][BN];
    int tid = threadIdx.x;
    int m0 = blockIdx.x * BM, n0 = blockIdx.y * BN;
    int tm = tid >> 4, tn = tid & 15;
    ull acc[4][4];
#pragma unroll
    for (int i = 0; i < 4; ++i)
#pragma unroll
        for (int j = 0; j < 4; ++j) acc[i][j] = 0ull;

    for (int k0 = 0; k0 < Cin; k0 += BK) {
        {   // A tile: padded rows are zero; garbage tail cols are zeroed via B guard
            int row = tid >> 2, kq = (tid & 3) * 4;
#pragma unroll
            for (int r = 0; r < 2; ++r) {
                int m = row + 64 * r;
                float4 v = *(const float4*)&H[(size_t)(m0 + m) * sH + k0 + kq];
                As[kq + 0][m] = v.x; As[kq + 1][m] = v.y;
                As[kq + 2][m] = v.z; As[kq + 3][m] = v.w;
            }
        }
        {   // B tile, guarded both dims, stored duplicated
            int n = tid & 63, kb = tid >> 6;
#pragma unroll
            for (int r = 0; r < 4; ++r) {
                int k = kb + 4 * r;
                int gk = k0 + k, gn = n0 + n;
                float v = (gk < Cin && gn < Cout) ? __ldg(&B[(size_t)gk * Cout + gn]) : 0.f;
                Bs2[k][n] = dup2(v);
            }
        }
        __syncthreads();
#pragma unroll
        for (int kk = 0; kk < BK; ++kk) {
            ulonglong2 a01 = *(const ulonglong2*)&As[kk][tm * 8];
            ulonglong2 a23 = *(const ulonglong2*)&As[kk][tm * 8 + 4];
            ulonglong2 b01 = *(const ulonglong2*)&Bs2[kk][tn * 4];
            ulonglong2 b23 = *(const ulonglong2*)&Bs2[kk][tn * 4 + 2];
            ull av[4] = {a01.x, a01.y, a23.x, a23.y};
            ull bv[4] = {b01.x, b01.y, b23.x, b23.y};
#pragma unroll
            for (int i = 0; i < 4; ++i)
#pragma unroll
                for (int j = 0; j < 4; ++j) acc[i][j] = fma2(av[i], bv[j], acc[i][j]);
        }
        __syncthreads();
    }
#pragma unroll
    for (int i = 0; i < 4; ++i) {
#pragma unroll
        for (int j = 0; j < 4; ++j) {
            int gn = n0 + tn * 4 + j;
            if (gn >= Cout) continue;
            float2 p = unpack2(acc[i][j]);
            int gm0 = m0 + tm * 8 + 2 * i;
            float pv[2] = {p.x, p.y};
#pragma unroll
            for (int h = 0; h < 2; ++h) {
                int gm = gm0 + h;
                if (gm >= NN) continue;
                if (MODE == 0) {
                    D[(size_t)gm * sD + gn] = pv[h];
                } else if (MODE == 1) {
                    D[(size_t)gm * sD + gn] += pv[h];
                } else {
                    float r = D[(size_t)gm * sD + gn] + pv[h] + bias[gn];
                    D2[(size_t)gm * sD2 + gn] = fmaxf(r, 0.f);
                }
            }
        }
    }
}

// ---------------- layer 1 (Cin=1): fused scalar prop + rank-1 update ----------
__global__ void __launch_bounds__(256) k_l1_out0(const float* __restrict__ x,
                                                 const float* __restrict__ W0,
                                                 const float* __restrict__ b) {
    int w = (blockIdx.x * 256 + threadIdx.x) >> 5;
    if (w >= NN) return;
    int lane = threadIdx.x & 31;
    float xv = x[w];
    g_AC[(size_t)w * 64 + lane] = xv * W0[lane] + b[lane];
    int c = lane + 32;
    if (c < 60) g_AC[(size_t)w * 64 + c] = xv * W0[c] + b[c];
}
__global__ void __launch_bounds__(256) k_l1_step(const float* __restrict__ hold,
                                                 float* __restrict__ hnew,
                                                 const float* __restrict__ Wk) {
    int w = (blockIdx.x * 256 + threadIdx.x) >> 5;
    if (w >= NN) return;
    int lane = threadIdx.x & 31;
    int beg = g_rowptr[w], end = g_rowptr[w + 1];
    float s = 0.f;
    for (int p = beg + lane; p < end; p += 32) {
        float2 cv = __ldg(&g_cv[p]);
        s += cv.y * __ldg(&hold[__float_as_int(cv.x)]);
    }
#pragma unroll
    for (int o = 16; o; o >>= 1) s += __shfl_xor_sync(0xffffffffu, s, o);
    if (lane == 0) hnew[w] = s;
    g_AC[(size_t)w * 64 + lane] += s * Wk[lane];
    int c = lane + 32;
    if (c < 60) g_AC[(size_t)w * 64 + c] += s * Wk[c];
}

// ---------------- layer 5 (Cout=1): fused scalar Horner step + GEMV -----------
__global__ void __launch_bounds__(256) k_l5(const float* __restrict__ X,
                                            const float* __restrict__ Wk,
                                            const float* __restrict__ told,
                                            float* __restrict__ tnew, int first) {
    int w = (blockIdx.x * 256 + threadIdx.x) >> 5;
    if (w >= NN) return;
    int lane = threadIdx.x & 31;
    float s = 0.f;
    if (!first) {
        int beg = g_rowptr[w], end = g_rowptr[w + 1];
        for (int p = beg + lane; p < end; p += 32) {
            float2 cv = __ldg(&g_cv[p]);
            s += cv.y * __ldg(&told[__float_as_int(cv.x)]);
        }
    }
    const float* xr = X + (size_t)w * 96;
    s += xr[lane] * Wk[lane] + xr[lane + 32] * Wk[lane + 32];
    if (lane < 16) s += xr[lane + 64] * Wk[lane + 64];
#pragma unroll
    for (int o = 16; o; o >>= 1) s += __shfl_xor_sync(0xffffffffu, s, o);
    if (lane == 0) tnew[w] = s;
}

// ---------------- misc ----------------
__global__ void __launch_bounds__(256) k_relu(const float* __restrict__ src, int si,
                                              float* __restrict__ dst, int so, int C) {
    int w = (blockIdx.x * 256 + threadIdx.x) >> 5;
    if (w >= NN) return;
    int lane = threadIdx.x & 31;
    for (int c = lane; c < C; c += 32)
        dst[(size_t)w * so + c] = fmaxf(src[(size_t)w * si + c], 0.f);
}
__global__ void k_sigmoid(const float* __restrict__ t, const float* __restrict__ b,
                          float* __restrict__ out) {
    int i = blockIdx.x * blockDim.x + threadIdx.x;
    if (i < NN) out[i] = 1.f / (1.f + expf(-(t[i] + b[0])));
}

// ---------------- host ----------------
static inline void gemm0(const float* H, int sH, int Cin, const float* B, int Cout,
                         float* D, int sD) {
    dim3 g(RPAD / BM, (Cout + BN - 1) / BN);
    k_gemm<0><<<g, 256>>>(H, sH, Cin, B, Cout, D, sD, 0, 0, 0);
}
static inline void gemm1(const float* H, int sH, int Cin, const float* B, int Cout,
                         float* D, int sD) {
    dim3 g(RPAD / BM, (Cout + BN - 1) / BN);
    k_gemm<1><<<g, 256>>>(H, sH, Cin, B, Cout, D, sD, 0, 0, 0);
}
static inline void gemm2(const float* H, int sH, int Cin, const float* B, int Cout,
                         float* D, int sD, const float* bias, float* D2, int sD2) {
    dim3 g(RPAD / BM, (Cout + BN - 1) / BN);
    k_gemm<2><<<g, 256>>>(H, sH, Cin, B, Cout, D, sD, bias, D2, sD2);
}

extern "C" void kernel_launch(void* const* d_in, const int* in_sizes, int n_in,
                              void* d_out, int out_size) {
    const float* x  = (const float*)d_in[0];
    const int*   ei = (const int*)d_in[1];
    const float* ew = (const float*)d_in[2];
    const float* Wl[5]; const float* bl[5];
    for (int l = 0; l < 5; ++l) {
        Wl[l] = (const float*)d_in[3 + 2 * l];
        bl[l] = (const float*)d_in[4 + 2 * l];
    }
    float* out = (float*)d_out;

    float *XL, *A0, *A1, *AC;
    cudaGetSymbolAddress((void**)&XL, g_XL);
    cudaGetSymbolAddress((void**)&A0, g_A0);
    cudaGetSymbolAddress((void**)&A1, g_A1);
    cudaGetSymbolAddress((void**)&AC, g_AC);

    const int WG = (NN * 32 + 255) / 256;   // warp-per-node grid

    // ---- CSR build (coalesced multi-block scan) ----
    k_zero_nodes<<<(NN + 255) / 256, 256>>>();
    k_degcnt<<<(EE + 255) / 256, 256>>>(ei, ew);
    k_dis<<<(NN + 255) / 256, 256>>>();
    k_bsum<<<SBLK, 256>>>();
    k_bscan<<<1, 256>>>();
    k_wptr<<<SBLK, 256>>>();
    k_scatter<<<(EE + 255) / 256, 256>>>(ei, ew);

    // ---- layer 1: Cin=1, Cout=60 — scalar prop + fused GEMV into AC(64) ----
    k_l1_out0<<<WG, 256>>>(x, Wl[0], bl[0]);
    {
        const float* hold = x;
        float* hnew = A0;
        for (int k = 1; k <= KH; ++k) {
            k_l1_step<<<WG, 256>>>(hold, hnew, Wl[0] + (size_t)k * 60);
            hold = hnew;
            hnew = (hnew == A0) ? A1 : A0;
        }
    }
    k_relu<<<WG, 256>>>(AC, 64, XL, 64, 60);

    // ---- layer 2: Cin=60 (CH=2, s=64), Cout=100 (AC stride 128) ----
    gemm0(XL, 64, 60, Wl[1], 100, AC, 128);
    {
        const float* hin = XL;
        float* hop = A0;
        for (int k = 1; k <= KH; ++k) {
            k_prop<2><<<WG, 256>>>(hin, hop);
            if (k < KH) gemm1(hop, 64, 60, Wl[1] + (size_t)k * 6000, 100, AC, 128);
            else        gemm2(hop, 64, 60, Wl[1] + (size_t)k * 6000, 100, AC, 128,
                              bl[1], XL, 128);
            hin = hop;
            hop = (hop == A0) ? A1 : A0;
        }
    }

    // ---- layer 3: Cin=100 (CH=4, s=128), Cout=200 (AC stride 224) ----
    gemm0(XL, 128, 100, Wl[2], 200, AC, 224);
    {
        const float* hin = XL;
        float* hop = A0;
        for (int k = 1; k <= KH; ++k) {
            k_prop<4><<<WG, 256>>>(hin, hop);
            if (k < KH) gemm1(hop, 128, 100, Wl[2] + (size_t)k * 20000, 200, AC, 224);
            else        gemm2(hop, 128, 100, Wl[2] + (size_t)k * 20000, 200, AC, 224,
                              bl[2], XL, 224);
            hin = hop;
            hop = (hop == A0) ? A1 : A0;
        }
    }

    // ---- layer 4: Cin=200, Cout=80 — Horner in output space (CH=3, s=96) ----
    gemm0(XL, 224, 200, Wl[3] + (size_t)KH * 16000, 80, A0, 96);
    {
        float* t = A0;
        float* o = A1;
        for (int k = KH - 1; k >= 0; --k) {
            k_prop<3><<<WG, 256>>>(t, o);
            if (k > 0) gemm1(XL, 224, 200, Wl[3] + (size_t)k * 16000, 80, o, 96);
            else       gemm2(XL, 224, 200, Wl[3], 80, o, 96, bl[3], AC, 96);
            float* tmp = t; t = o; o = tmp;
        }
    }

    // ---- layer 5: Cin=80 (X = AC stride 96), Cout=1 — fused Horner ----
    {
        float* tA = A0;
        float* tB = A1;
        k_l5<<<WG, 256>>>(AC, Wl[4] + (size_t)KH * 80, 0, tA, 1);
        const float* hold = tA;
        float* cur = tB;
        float* nxt = tA;
        for (int k = KH - 1; k >= 0; --k) {
            k_l5<<<WG, 256>>>(AC, Wl[4] + (size_t)k * 80, hold, cur, 0);
            hold = cur;
            float* tmp = cur; cur = nxt; nxt = tmp;
        }
        k_sigmoid<<<(NN + 255) / 256, 256>>>(hold, bl[4], out);
    }
}

// round 5
// speedup vs baseline: 1.2575x; 1.2575x over previous
#include <cuda_runtime.h>
#include <math.h>

#define NN 50000
#define RPAD 50176
#define EE 800000
#define KH 20
#define SBLK 196          // ceil(NN/256)

// ---------------- scratch (device globals; zero-init at module load) ---------
__device__ float g_XL[(size_t)RPAD * 224];  // layer input/activations
__device__ float g_A0[(size_t)RPAD * 224];  // hop ping
__device__ float g_A1[(size_t)RPAD * 224];  // hop pong
__device__ float g_AC[(size_t)RPAD * 224];  // accumulator
__device__ float  g_deg[NN];
__device__ float  g_dis[NN];
__device__ int    g_cnt[NN];
__device__ int    g_rowptr[NN + 1];
__device__ int    g_cursor[NN];
__device__ int    g_bsum[256];
__device__ int    g_boff[256];
__device__ float2 g_cv[EE];

// ---------------- CSR build ----------------
__global__ void k_zero_nodes() {
    int i = blockIdx.x * blockDim.x + threadIdx.x;
    if (i < NN) { g_deg[i] = 0.f; g_cnt[i] = 0; }
}
__global__ void k_degcnt(const int* __restrict__ ei, const float* __restrict__ ew) {
    int e = blockIdx.x * blockDim.x + threadIdx.x;
    if (e < EE) {
        int d = ei[EE + e];
        atomicAdd(&g_deg[d], ew[e]);
        atomicAdd(&g_cnt[d], 1);
    }
}
__global__ void k_dis() {
    int i = blockIdx.x * blockDim.x + threadIdx.x;
    if (i < NN) {
        float d = g_deg[i];
        g_dis[i] = (d > 0.f) ? rsqrtf(d) : 0.f;
    }
}
__global__ void k_bsum() {
    __shared__ int sh[256];
    int t = threadIdx.x, i = blockIdx.x * 256 + t;
    sh[t] = (i < NN) ? g_cnt[i] : 0;
    __syncthreads();
    for (int o = 128; o; o >>= 1) {
        if (t < o) sh[t] += sh[t + o];
        __syncthreads();
    }
    if (!t) g_bsum[blockIdx.x] = sh[0];
}
__global__ void k_bscan() {
    __shared__ int sh[256];
    int t = threadIdx.x;
    int v = (t < SBLK) ? g_bsum[t] : 0;
    sh[t] = v;
    __syncthreads();
    for (int o = 1; o < 256; o <<= 1) {
        int u = (t >= o) ? sh[t - o] : 0;
        __syncthreads();
        sh[t] += u;
        __syncthreads();
    }
    if (t < SBLK) g_boff[t] = sh[t] - v;
}
__global__ void k_wptr() {
    __shared__ int sh[256];
    int t = threadIdx.x, i = blockIdx.x * 256 + t;
    int v = (i < NN) ? g_cnt[i] : 0;
    sh[t] = v;
    __syncthreads();
    for (int o = 1; o < 256; o <<= 1) {
        int u = (t >= o) ? sh[t - o] : 0;
        __syncthreads();
        sh[t] += u;
        __syncthreads();
    }
    int excl = sh[t] - v + g_boff[blockIdx.x];
    if (i < NN) {
        g_rowptr[i] = excl;
        g_cursor[i] = excl;
        if (i == NN - 1) g_rowptr[NN] = excl + v;
    }
}
__global__ void k_scatter(const int* __restrict__ ei, const float* __restrict__ ew) {
    int e = blockIdx.x * blockDim.x + threadIdx.x;
    if (e < EE) {
        int s = ei[e];
        int d = ei[EE + e];
        int p = atomicAdd(&g_cursor[d], 1);
        float2 cv;
        cv.x = __int_as_float(s);
        cv.y = g_dis[s] * ew[e] * g_dis[d];
        g_cv[p] = cv;
    }
}

// ---------------- vector propagation: warp/node, CH 32-wide chunks -----------
template <int CH>
__global__ void __launch_bounds__(256) k_prop(const float* __restrict__ hin,
                                              float* __restrict__ hout) {
    int w = (blockIdx.x * 256 + threadIdx.x) >> 5;
    if (w >= NN) return;
    int lane = threadIdx.x & 31;
    int beg = g_rowptr[w], end = g_rowptr[w + 1];
    const int S = CH * 32;
    float acc[CH];
#pragma unroll
    for (int t = 0; t < CH; ++t) acc[t] = 0.f;
    int p = beg;
    for (; p + 2 <= end; p += 2) {
        float2 cv0 = __ldg(&g_cv[p]);
        float2 cv1 = __ldg(&g_cv[p + 1]);
        const float* r0 = hin + (size_t)__float_as_int(cv0.x) * S + lane;
        const float* r1 = hin + (size_t)__float_as_int(cv1.x) * S + lane;
#pragma unroll
        for (int t = 0; t < CH; ++t) acc[t] += cv0.y * __ldg(r0 + 32 * t);
#pragma unroll
        for (int t = 0; t < CH; ++t) acc[t] += cv1.y * __ldg(r1 + 32 * t);
    }
    if (p < end) {
        float2 cv = __ldg(&g_cv[p]);
        const float* r = hin + (size_t)__float_as_int(cv.x) * S + lane;
#pragma unroll
        for (int t = 0; t < CH; ++t) acc[t] += cv.y * __ldg(r + 32 * t);
    }
    float* o = hout + (size_t)w * S + lane;
#pragma unroll
    for (int t = 0; t < CH; ++t) o[32 * t] = acc[t];
}

// ---------------- GEMM: 128 x (16*TN) tile, 8 x TN microtile, NH hop sources --
// MODE 0: D = P          MODE 1: D += P          MODE 2: D2 = relu(D + P + bias)
// P = sum_h H_h @ W_h  where W_h = W + h*Cin*Cout  (consecutive hop weight slices)
#define BM 128
#define BK 16
template <int TN, int MODE, int NH>
__global__ void __launch_bounds__(256) k_gemm(const float* __restrict__ H0,
                                              const float* __restrict__ H1,
                                              int sH, int Cin,
                                              const float* __restrict__ W, int Cout,
                                              float* __restrict__ D, int sD,
                                              const float* __restrict__ bias,
                                              float* __restrict__ D2, int sD2) {
    const int BN = 16 * TN;
    __shared__ float As[BK][BM + 4];
    __shared__ float Bs[BK][BN];
    int tid = threadIdx.x;
    int m0 = blockIdx.x * BM, n0 = blockIdx.y * BN;
    int tm = tid >> 4, tn = tid & 15;
    float acc[8][TN];
#pragma unroll
    for (int i = 0; i < 8; ++i)
#pragma unroll
        for (int j = 0; j < TN; ++j) acc[i][j] = 0.f;

#pragma unroll
    for (int h = 0; h < NH; ++h) {
        const float* H = (h == 0) ? H0 : H1;
        const float* Wh = W + (size_t)h * Cin * Cout;
        for (int k0 = 0; k0 < Cin; k0 += BK) {
            {   // A tile: rows padded; over-read cols are zeroed via B guard
                int row = tid >> 2, kq = (tid & 3) * 4;
#pragma unroll
                for (int r = 0; r < 2; ++r) {
                    int m = row + 64 * r;
                    float4 v = *(const float4*)&H[(size_t)(m0 + m) * sH + k0 + kq];
                    As[kq + 0][m] = v.x; As[kq + 1][m] = v.y;
                    As[kq + 2][m] = v.z; As[kq + 3][m] = v.w;
                }
            }
            {   // B tile, guarded both dims
                for (int e = tid; e < BK * BN; e += 256) {
                    int k = e / BN, n = e - k * BN;
                    int gk = k0 + k, gn = n0 + n;
                    Bs[k][n] = (gk < Cin && gn < Cout)
                                   ? __ldg(&Wh[(size_t)gk * Cout + gn]) : 0.f;
                }
            }
            __syncthreads();
#pragma unroll
            for (int kk = 0; kk < BK; ++kk) {
                float4 a0 = *(const float4*)&As[kk][tm * 8];
                float4 a1 = *(const float4*)&As[kk][tm * 8 + 4];
                float av[8] = {a0.x, a0.y, a0.z, a0.w, a1.x, a1.y, a1.z, a1.w};
                float bv[TN];
#pragma unroll
                for (int j = 0; j < TN; ++j) bv[j] = Bs[kk][tn * TN + j];
#pragma unroll
                for (int i = 0; i < 8; ++i)
#pragma unroll
                    for (int j = 0; j < TN; ++j) acc[i][j] += av[i] * bv[j];
            }
            __syncthreads();
        }
    }
#pragma unroll
    for (int i = 0; i < 8; ++i) {
        int gm = m0 + tm * 8 + i;
        if (gm >= NN) continue;
#pragma unroll
        for (int j = 0; j < TN; ++j) {
            int gn = n0 + tn * TN + j;
            if (gn >= Cout) continue;
            if (MODE == 0) {
                D[(size_t)gm * sD + gn] = acc[i][j];
            } else if (MODE == 1) {
                D[(size_t)gm * sD + gn] += acc[i][j];
            } else {
                float r = D[(size_t)gm * sD + gn] + acc[i][j] + bias[gn];
                D2[(size_t)gm * sD2 + gn] = fmaxf(r, 0.f);
            }
        }
    }
}

// ---------------- layer 1 (Cin=1): fused scalar prop + rank-1 update ----------
__global__ void __launch_bounds__(256) k_l1_out0(const float* __restrict__ x,
                                                 const float* __restrict__ W0,
                                                 const float* __restrict__ b) {
    int w = (blockIdx.x * 256 + threadIdx.x) >> 5;
    if (w >= NN) return;
    int lane = threadIdx.x & 31;
    float xv = x[w];
    g_AC[(size_t)w * 64 + lane] = xv * W0[lane] + b[lane];
    int c = lane + 32;
    if (c < 60) g_AC[(size_t)w * 64 + c] = xv * W0[c] + b[c];
}
__global__ void __launch_bounds__(256) k_l1_step(const float* __restrict__ hold,
                                                 float* __restrict__ hnew,
                                                 const float* __restrict__ Wk) {
    int w = (blockIdx.x * 256 + threadIdx.x) >> 5;
    if (w >= NN) return;
    int lane = threadIdx.x & 31;
    int beg = g_rowptr[w], end = g_rowptr[w + 1];
    float s = 0.f;
    for (int p = beg + lane; p < end; p += 32) {
        float2 cv = __ldg(&g_cv[p]);
        s += cv.y * __ldg(&hold[__float_as_int(cv.x)]);
    }
#pragma unroll
    for (int o = 16; o; o >>= 1) s += __shfl_xor_sync(0xffffffffu, s, o);
    if (lane == 0) hnew[w] = s;
    g_AC[(size_t)w * 64 + lane] += s * Wk[lane];
    int c = lane + 32;
    if (c < 60) g_AC[(size_t)w * 64 + c] += s * Wk[c];
}

// ---------------- layer 5 (Cout=1): fused scalar Horner step + GEMV -----------
__global__ void __launch_bounds__(256) k_l5(const float* __restrict__ X,
                                            const float* __restrict__ Wk,
                                            const float* __restrict__ told,
                                            float* __restrict__ tnew, int first) {
    int w = (blockIdx.x * 256 + threadIdx.x) >> 5;
    if (w >= NN) return;
    int lane = threadIdx.x & 31;
    float s = 0.f;
    if (!first) {
        int beg = g_rowptr[w], end = g_rowptr[w + 1];
        for (int p = beg + lane; p < end; p += 32) {
            float2 cv = __ldg(&g_cv[p]);
            s += cv.y * __ldg(&told[__float_as_int(cv.x)]);
        }
    }
    const float* xr = X + (size_t)w * 96;
    s += xr[lane] * Wk[lane] + xr[lane + 32] * Wk[lane + 32];
    if (lane < 16) s += xr[lane + 64] * Wk[lane + 64];
#pragma unroll
    for (int o = 16; o; o >>= 1) s += __shfl_xor_sync(0xffffffffu, s, o);
    if (lane == 0) tnew[w] = s;
}

// ---------------- misc ----------------
__global__ void __launch_bounds__(256) k_relu(const float* __restrict__ src, int si,
                                              float* __restrict__ dst, int so, int C) {
    int w = (blockIdx.x * 256 + threadIdx.x) >> 5;
    if (w >= NN) return;
    int lane = threadIdx.x & 31;
    for (int c = lane; c < C; c += 32)
        dst[(size_t)w * so + c] = fmaxf(src[(size_t)w * si + c], 0.f);
}
__global__ void k_sigmoid(const float* __restrict__ t, const float* __restrict__ b,
                          float* __restrict__ out) {
    int i = blockIdx.x * blockDim.x + threadIdx.x;
    if (i < NN) out[i] = 1.f / (1.f + expf(-(t[i] + b[0])));
}

// ---------------- host ----------------
extern "C" void kernel_launch(void* const* d_in, const int* in_sizes, int n_in,
                              void* d_out, int out_size) {
    const float* x  = (const float*)d_in[0];
    const int*   ei = (const int*)d_in[1];
    const float* ew = (const float*)d_in[2];
    const float* Wl[5]; const float* bl[5];
    for (int l = 0; l < 5; ++l) {
        Wl[l] = (const float*)d_in[3 + 2 * l];
        bl[l] = (const float*)d_in[4 + 2 * l];
    }
    float* out = (float*)d_out;

    float *XL, *A0, *A1, *AC;
    cudaGetSymbolAddress((void**)&XL, g_XL);
    cudaGetSymbolAddress((void**)&A0, g_A0);
    cudaGetSymbolAddress((void**)&A1, g_A1);
    cudaGetSymbolAddress((void**)&AC, g_AC);

    const int WG = (NN * 32 + 255) / 256;   // warp-per-node grid
    const int GM = RPAD / BM;               // 392 m-blocks

    // ---- CSR build (coalesced multi-block scan) ----
    k_zero_nodes<<<(NN + 255) / 256, 256>>>();
    k_degcnt<<<(EE + 255) / 256, 256>>>(ei, ew);
    k_dis<<<(NN + 255) / 256, 256>>>();
    k_bsum<<<SBLK, 256>>>();
    k_bscan<<<1, 256>>>();
    k_wptr<<<SBLK, 256>>>();
    k_scatter<<<(EE + 255) / 256, 256>>>(ei, ew);

    // ---- layer 1: Cin=1, Cout=60 — scalar prop + fused GEMV into AC(64) ----
    k_l1_out0<<<WG, 256>>>(x, Wl[0], bl[0]);
    {
        const float* hold = x;
        float* hnew = A0;
        for (int k = 1; k <= KH; ++k) {
            k_l1_step<<<WG, 256>>>(hold, hnew, Wl[0] + (size_t)k * 60);
            hold = hnew;
            hnew = (hnew == A0) ? A1 : A0;
        }
    }
    k_relu<<<WG, 256>>>(AC, 64, XL, 64, 60);

    // ---- layer 2: Cin=60 (S=64), Cout=100 — paired-hop GEMMs, TN=7 (BN=112) ----
    {
        dim3 g(GM, 1);
        k_prop<2><<<WG, 256>>>(XL, A0);                                   // hop1
        k_gemm<7, 0, 2><<<g, 256>>>(XL, A0, 64, 60, Wl[1], 100, AC, 112, 0, 0, 0);
        for (int j = 1; j <= 9; ++j) {                                    // hops 2j, 2j+1
            k_prop<2><<<WG, 256>>>(A0, A1);
            k_prop<2><<<WG, 256>>>(A1, A0);
            k_gemm<7, 1, 2><<<g, 256>>>(A1, A0, 64, 60, Wl[1] + (size_t)(2 * j) * 6000,
                                        100, AC, 112, 0, 0, 0);
        }
        k_prop<2><<<WG, 256>>>(A0, A1);                                   // hop20
        k_gemm<7, 2, 1><<<g, 256>>>(A1, 0, 64, 60, Wl[1] + (size_t)KH * 6000,
                                    100, AC, 112, bl[1], XL, 128);
    }

    // ---- layer 3: Cin=100 (S=128), Cout=200 — paired-hop GEMMs, TN=7 ----
    {
        dim3 g(GM, 2);
        k_prop<4><<<WG, 256>>>(XL, A0);
        k_gemm<7, 0, 2><<<g, 256>>>(XL, A0, 128, 100, Wl[2], 200, AC, 224, 0, 0, 0);
        for (int j = 1; j <= 9; ++j) {
            k_prop<4><<<WG, 256>>>(A0, A1);
            k_prop<4><<<WG, 256>>>(A1, A0);
            k_gemm<7, 1, 2><<<g, 256>>>(A1, A0, 128, 100, Wl[2] + (size_t)(2 * j) * 20000,
                                        200, AC, 224, 0, 0, 0);
        }
        k_prop<4><<<WG, 256>>>(A0, A1);
        k_gemm<7, 2, 1><<<g, 256>>>(A1, 0, 128, 100, Wl[2] + (size_t)KH * 20000,
                                    200, AC, 224, bl[2], XL, 224);
    }

    // ---- layer 4: Cin=200, Cout=80 — Horner in output space, TN=5 (BN=80) ----
    {
        dim3 g(GM, 1);
        float* t = A0;
        float* o = A1;
        k_gemm<5, 0, 1><<<g, 256>>>(XL, 0, 224, 200, Wl[3] + (size_t)KH * 16000,
                                    80, t, 96, 0, 0, 0);
        for (int k = KH - 1; k >= 1; --k) {
            k_prop<3><<<WG, 256>>>(t, o);
            k_gemm<5, 1, 1><<<g, 256>>>(XL, 0, 224, 200, Wl[3] + (size_t)k * 16000,
                                        80, o, 96, 0, 0, 0);
            float* tmp = t; t = o; o = tmp;
        }
        k_prop<3><<<WG, 256>>>(t, o);
        k_gemm<5, 2, 1><<<g, 256>>>(XL, 0, 224, 200, Wl[3], 80, o, 96, bl[3], AC, 96);
    }

    // ---- layer 5: Cin=80 (X = AC stride 96), Cout=1 — fused Horner ----
    {
        float* tA = A0;
        float* tB = A1;
        k_l5<<<WG, 256>>>(AC, Wl[4] + (size_t)KH * 80, 0, tA, 1);
        const float* hold = tA;
        float* cur = tB;
        float* nxt = tA;
        for (int k = KH - 1; k >= 0; --k) {
            k_l5<<<WG, 256>>>(AC, Wl[4] + (size_t)k * 80, hold, cur, 0);
            hold = cur;
            float* tmp = cur; cur = nxt; nxt = tmp;
        }
        k_sigmoid<<<(NN + 255) / 256, 256>>>(hold, bl[4], out);
    }
}

// round 6
// speedup vs baseline: 1.4795x; 1.1765x over previous
#include <cuda_runtime.h>
#include <math.h>

#define NN 50000
#define RPAD 50176
#define EE 800000
#define KH 20
#define SBLK 196          // ceil(NN/256)

// ---------------- scratch (device globals; zero-init at module load) ---------
__device__ float g_XL[(size_t)RPAD * 224];  // layer input/activations
__device__ float g_A0[(size_t)RPAD * 224];  // hop ping
__device__ float g_A1[(size_t)RPAD * 224];  // hop pong
__device__ float g_AC[(size_t)RPAD * 224];  // accumulator
__device__ float  g_deg[NN];
__device__ float  g_dis[NN];
__device__ int    g_cnt[NN];
__device__ int    g_rowptr[NN + 1];
__device__ int    g_cursor[NN];
__device__ int    g_bsum[256];
__device__ int    g_boff[256];
__device__ float2 g_cv[EE];

// ---------------- CSR build ----------------
__global__ void k_zero_nodes() {
    int i = blockIdx.x * blockDim.x + threadIdx.x;
    if (i < NN) { g_deg[i] = 0.f; g_cnt[i] = 0; }
}
__global__ void k_degcnt(const int* __restrict__ ei, const float* __restrict__ ew) {
    int e = blockIdx.x * blockDim.x + threadIdx.x;
    if (e < EE) {
        int d = ei[EE + e];
        atomicAdd(&g_deg[d], ew[e]);
        atomicAdd(&g_cnt[d], 1);
    }
}
__global__ void k_dis() {
    int i = blockIdx.x * blockDim.x + threadIdx.x;
    if (i < NN) {
        float d = g_deg[i];
        g_dis[i] = (d > 0.f) ? rsqrtf(d) : 0.f;
    }
}
__global__ void k_bsum() {
    __shared__ int sh[256];
    int t = threadIdx.x, i = blockIdx.x * 256 + t;
    sh[t] = (i < NN) ? g_cnt[i] : 0;
    __syncthreads();
    for (int o = 128; o; o >>= 1) {
        if (t < o) sh[t] += sh[t + o];
        __syncthreads();
    }
    if (!t) g_bsum[blockIdx.x] = sh[0];
}
__global__ void k_bscan() {
    __shared__ int sh[256];
    int t = threadIdx.x;
    int v = (t < SBLK) ? g_bsum[t] : 0;
    sh[t] = v;
    __syncthreads();
    for (int o = 1; o < 256; o <<= 1) {
        int u = (t >= o) ? sh[t - o] : 0;
        __syncthreads();
        sh[t] += u;
        __syncthreads();
    }
    if (t < SBLK) g_boff[t] = sh[t] - v;
}
__global__ void k_wptr() {
    __shared__ int sh[256];
    int t = threadIdx.x, i = blockIdx.x * 256 + t;
    int v = (i < NN) ? g_cnt[i] : 0;
    sh[t] = v;
    __syncthreads();
    for (int o = 1; o < 256; o <<= 1) {
        int u = (t >= o) ? sh[t - o] : 0;
        __syncthreads();
        sh[t] += u;
        __syncthreads();
    }
    int excl = sh[t] - v + g_boff[blockIdx.x];
    if (i < NN) {
        g_rowptr[i] = excl;
        g_cursor[i] = excl;
        if (i == NN - 1) g_rowptr[NN] = excl + v;
    }
}
__global__ void k_scatter(const int* __restrict__ ei, const float* __restrict__ ew) {
    int e = blockIdx.x * blockDim.x + threadIdx.x;
    if (e < EE) {
        int s = ei[e];
        int d = ei[EE + e];
        int p = atomicAdd(&g_cursor[d], 1);
        float2 cv;
        cv.x = __int_as_float(s);
        cv.y = g_dis[s] * ew[e] * g_dis[d];
        g_cv[p] = cv;
    }
}

// ---------------- vector propagation: warp/node, CH 32-wide chunks -----------
template <int CH>
__global__ void __launch_bounds__(256) k_prop(const float* __restrict__ hin,
                                              float* __restrict__ hout) {
    int w = (blockIdx.x * 256 + threadIdx.x) >> 5;
    if (w >= NN) return;
    int lane = threadIdx.x & 31;
    int beg = g_rowptr[w], end = g_rowptr[w + 1];
    const int S = CH * 32;
    float acc[CH];
#pragma unroll
    for (int t = 0; t < CH; ++t) acc[t] = 0.f;
    int p = beg;
    for (; p + 2 <= end; p += 2) {
        float2 cv0 = __ldg(&g_cv[p]);
        float2 cv1 = __ldg(&g_cv[p + 1]);
        const float* r0 = hin + (size_t)__float_as_int(cv0.x) * S + lane;
        const float* r1 = hin + (size_t)__float_as_int(cv1.x) * S + lane;
#pragma unroll
        for (int t = 0; t < CH; ++t) acc[t] += cv0.y * __ldg(r0 + 32 * t);
#pragma unroll
        for (int t = 0; t < CH; ++t) acc[t] += cv1.y * __ldg(r1 + 32 * t);
    }
    if (p < end) {
        float2 cv = __ldg(&g_cv[p]);
        const float* r = hin + (size_t)__float_as_int(cv.x) * S + lane;
#pragma unroll
        for (int t = 0; t < CH; ++t) acc[t] += cv.y * __ldg(r + 32 * t);
    }
    float* o = hout + (size_t)w * S + lane;
#pragma unroll
    for (int t = 0; t < CH; ++t) o[32 * t] = acc[t];
}

// ---------------- GEMM: 128 x (16*TN) tile, 8 x TN microtile ----------------
// MODE 0: D = P      MODE 1: D += P      MODE 2: D2 = relu(D + P + bias)
// n-range starts at noff (for narrow remainder tiles).
#define BM 128
#define BK 16
template <int TN, int MODE>
__global__ void __launch_bounds__(256) k_gemm(const float* __restrict__ H, int sH, int Cin,
                                              const float* __restrict__ W, int Cout, int noff,
                                              float* __restrict__ D, int sD,
                                              const float* __restrict__ bias,
                                              float* __restrict__ D2, int sD2) {
    const int BN = 16 * TN;
    __shared__ float As[BK][BM + 4];
    __shared__ float Bs[BK][BN];
    int tid = threadIdx.x;
    int m0 = blockIdx.x * BM, n0 = noff + blockIdx.y * BN;
    int tm = tid >> 4, tn = tid & 15;
    float acc[8][TN];
#pragma unroll
    for (int i = 0; i < 8; ++i)
#pragma unroll
        for (int j = 0; j < TN; ++j) acc[i][j] = 0.f;

    for (int k0 = 0; k0 < Cin; k0 += BK) {
        {   // A tile: rows zero-padded; cols >= Cin neutralized via B guard
            int row = tid >> 2, kq = (tid & 3) * 4;
#pragma unroll
            for (int r = 0; r < 2; ++r) {
                int m = row + 64 * r;
                float4 v = *(const float4*)&H[(size_t)(m0 + m) * sH + k0 + kq];
                As[kq + 0][m] = v.x; As[kq + 1][m] = v.y;
                As[kq + 2][m] = v.z; As[kq + 3][m] = v.w;
            }
        }
        {   // B tile, guarded both dims
#pragma unroll
            for (int e = tid; e < BK * BN; e += 256) {
                int k = e / BN, n = e - k * BN;
                int gk = k0 + k, gn = n0 + n;
                Bs[k][n] = (gk < Cin && gn < Cout)
                               ? __ldg(&W[(size_t)gk * Cout + gn]) : 0.f;
            }
        }
        __syncthreads();
#pragma unroll
        for (int kk = 0; kk < BK; ++kk) {
            float4 a0 = *(const float4*)&As[kk][tm * 8];
            float4 a1 = *(const float4*)&As[kk][tm * 8 + 4];
            float av[8] = {a0.x, a0.y, a0.z, a0.w, a1.x, a1.y, a1.z, a1.w};
            float bv[TN];
            if (TN == 4) {
                float4 b = *(const float4*)&Bs[kk][tn * 4];
                bv[0] = b.x; bv[1] = b.y; bv[2] = b.z; bv[3] = b.w;
            } else {
#pragma unroll
                for (int j = 0; j < TN; ++j) bv[j] = Bs[kk][tn * TN + j];
            }
#pragma unroll
            for (int i = 0; i < 8; ++i)
#pragma unroll
                for (int j = 0; j < TN; ++j) acc[i][j] += av[i] * bv[j];
        }
        __syncthreads();
    }
#pragma unroll
    for (int i = 0; i < 8; ++i) {
        int gm = m0 + tm * 8 + i;
        if (gm >= NN) continue;
#pragma unroll
        for (int j = 0; j < TN; ++j) {
            int gn = n0 + tn * TN + j;
            if (gn >= Cout) continue;
            if (MODE == 0) {
                D[(size_t)gm * sD + gn] = acc[i][j];
            } else if (MODE == 1) {
                D[(size_t)gm * sD + gn] += acc[i][j];
            } else {
                float r = D[(size_t)gm * sD + gn] + acc[i][j] + bias[gn];
                D2[(size_t)gm * sD2 + gn] = fmaxf(r, 0.f);
            }
        }
    }
}

// ---------------- layer 1 (Cin=1): fused scalar prop + rank-1 update ----------
__global__ void __launch_bounds__(256) k_l1_out0(const float* __restrict__ x,
                                                 const float* __restrict__ W0,
                                                 const float* __restrict__ b) {
    int w = (blockIdx.x * 256 + threadIdx.x) >> 5;
    if (w >= NN) return;
    int lane = threadIdx.x & 31;
    float xv = x[w];
    g_AC[(size_t)w * 64 + lane] = xv * W0[lane] + b[lane];
    int c = lane + 32;
    if (c < 60) g_AC[(size_t)w * 64 + c] = xv * W0[c] + b[c];
}
__global__ void __launch_bounds__(256) k_l1_step(const float* __restrict__ hold,
                                                 float* __restrict__ hnew,
                                                 const float* __restrict__ Wk) {
    int w = (blockIdx.x * 256 + threadIdx.x) >> 5;
    if (w >= NN) return;
    int lane = threadIdx.x & 31;
    int beg = g_rowptr[w], end = g_rowptr[w + 1];
    float s = 0.f;
    for (int p = beg + lane; p < end; p += 32) {
        float2 cv = __ldg(&g_cv[p]);
        s += cv.y * __ldg(&hold[__float_as_int(cv.x)]);
    }
#pragma unroll
    for (int o = 16; o; o >>= 1) s += __shfl_xor_sync(0xffffffffu, s, o);
    if (lane == 0) hnew[w] = s;
    g_AC[(size_t)w * 64 + lane] += s * Wk[lane];
    int c = lane + 32;
    if (c < 60) g_AC[(size_t)w * 64 + c] += s * Wk[c];
}

// ---------------- layer 5 (Cout=1): fused scalar Horner step + GEMV -----------
__global__ void __launch_bounds__(256) k_l5(const float* __restrict__ X,
                                            const float* __restrict__ Wk,
                                            const float* __restrict__ told,
                                            float* __restrict__ tnew, int first) {
    int w = (blockIdx.x * 256 + threadIdx.x) >> 5;
    if (w >= NN) return;
    int lane = threadIdx.x & 31;
    float s = 0.f;
    if (!first) {
        int beg = g_rowptr[w], end = g_rowptr[w + 1];
        for (int p = beg + lane; p < end; p += 32) {
            float2 cv = __ldg(&g_cv[p]);
            s += cv.y * __ldg(&told[__float_as_int(cv.x)]);
        }
    }
    const float* xr = X + (size_t)w * 96;
    s += xr[lane] * Wk[lane] + xr[lane + 32] * Wk[lane + 32];
    if (lane < 16) s += xr[lane + 64] * Wk[lane + 64];
#pragma unroll
    for (int o = 16; o; o >>= 1) s += __shfl_xor_sync(0xffffffffu, s, o);
    if (lane == 0) tnew[w] = s;
}

// ---------------- misc ----------------
__global__ void __launch_bounds__(256) k_relu(const float* __restrict__ src, int si,
                                              float* __restrict__ dst, int so, int C) {
    int w = (blockIdx.x * 256 + threadIdx.x) >> 5;
    if (w >= NN) return;
    int lane = threadIdx.x & 31;
    for (int c = lane; c < C; c += 32)
        dst[(size_t)w * so + c] = fmaxf(src[(size_t)w * si + c], 0.f);
}
__global__ void k_sigmoid(const float* __restrict__ t, const float* __restrict__ b,
                          float* __restrict__ out) {
    int i = blockIdx.x * blockDim.x + threadIdx.x;
    if (i < NN) out[i] = 1.f / (1.f + expf(-(t[i] + b[0])));
}

// ---------------- host ----------------
extern "C" void kernel_launch(void* const* d_in, const int* in_sizes, int n_in,
                              void* d_out, int out_size) {
    const float* x  = (const float*)d_in[0];
    const int*   ei = (const int*)d_in[1];
    const float* ew = (const float*)d_in[2];
    const float* Wl[5]; const float* bl[5];
    for (int l = 0; l < 5; ++l) {
        Wl[l] = (const float*)d_in[3 + 2 * l];
        bl[l] = (const float*)d_in[4 + 2 * l];
    }
    float* out = (float*)d_out;

    float *XL, *A0, *A1, *AC;
    cudaGetSymbolAddress((void**)&XL, g_XL);
    cudaGetSymbolAddress((void**)&A0, g_A0);
    cudaGetSymbolAddress((void**)&A1, g_A1);
    cudaGetSymbolAddress((void**)&AC, g_AC);

    const int WG = (NN * 32 + 255) / 256;   // warp-per-node grid
    const int GM = RPAD / BM;               // 392 m-blocks

    // ---- CSR build (coalesced multi-block scan) ----
    k_zero_nodes<<<(NN + 255) / 256, 256>>>();
    k_degcnt<<<(EE + 255) / 256, 256>>>(ei, ew);
    k_dis<<<(NN + 255) / 256, 256>>>();
    k_bsum<<<SBLK, 256>>>();
    k_bscan<<<1, 256>>>();
    k_wptr<<<SBLK, 256>>>();
    k_scatter<<<(EE + 255) / 256, 256>>>(ei, ew);

    // ---- layer 1: Cin=1, Cout=60 — scalar prop + fused GEMV into AC(64) ----
    k_l1_out0<<<WG, 256>>>(x, Wl[0], bl[0]);
    {
        const float* hold = x;
        float* hnew = A0;
        for (int k = 1; k <= KH; ++k) {
            k_l1_step<<<WG, 256>>>(hold, hnew, Wl[0] + (size_t)k * 60);
            hold = hnew;
            hnew = (hnew == A0) ? A1 : A0;
        }
    }
    k_relu<<<WG, 256>>>(AC, 64, XL, 64, 60);

    // ---- layer 2: Cin=60 (S=64), Cout=100 — 2x64 wide tiles (R2 config) ----
    {
        dim3 g(GM, 2);
        k_gemm<4, 0><<<g, 256>>>(XL, 64, 60, Wl[1], 100, 0, AC, 128, 0, 0, 0);
        const float* hin = XL;
        float* hop = A0;
        for (int k = 1; k <= KH; ++k) {
            k_prop<2><<<WG, 256>>>(hin, hop);
            const float* Wk = Wl[1] + (size_t)k * 6000;
            if (k < KH) k_gemm<4, 1><<<g, 256>>>(hop, 64, 60, Wk, 100, 0, AC, 128, 0, 0, 0);
            else        k_gemm<4, 2><<<g, 256>>>(hop, 64, 60, Wk, 100, 0, AC, 128,
                                                 bl[1], XL, 128);
            hin = hop;
            hop = (hop == A0) ? A1 : A0;
        }
    }

    // ---- layer 3: Cin=100 (S=128), Cout=200 — 3x64 wide + 1x16 narrow ----
    {
        dim3 gw(GM, 3), gn(GM, 1);
        k_gemm<4, 0><<<gw, 256>>>(XL, 128, 100, Wl[2], 200, 0,   AC, 224, 0, 0, 0);
        k_gemm<1, 0><<<gn, 256>>>(XL, 128, 100, Wl[2], 200, 192, AC, 224, 0, 0, 0);
        const float* hin = XL;
        float* hop = A0;
        for (int k = 1; k <= KH; ++k) {
            k_prop<4><<<WG, 256>>>(hin, hop);
            const float* Wk = Wl[2] + (size_t)k * 20000;
            if (k < KH) {
                k_gemm<4, 1><<<gw, 256>>>(hop, 128, 100, Wk, 200, 0,   AC, 224, 0, 0, 0);
                k_gemm<1, 1><<<gn, 256>>>(hop, 128, 100, Wk, 200, 192, AC, 224, 0, 0, 0);
            } else {
                k_gemm<4, 2><<<gw, 256>>>(hop, 128, 100, Wk, 200, 0,   AC, 224,
                                          bl[2], XL, 224);
                k_gemm<1, 2><<<gn, 256>>>(hop, 128, 100, Wk, 200, 192, AC, 224,
                                          bl[2], XL, 224);
            }
            hin = hop;
            hop = (hop == A0) ? A1 : A0;
        }
    }

    // ---- layer 4: Cin=200, Cout=80 — Horner output space, 1x64 + 1x16 ----
    {
        dim3 g1(GM, 1);
        float* t = A0;
        float* o = A1;
        const float* Wt = Wl[3] + (size_t)KH * 16000;
        k_gemm<4, 0><<<g1, 256>>>(XL, 224, 200, Wt, 80, 0,  t, 96, 0, 0, 0);
        k_gemm<1, 0><<<g1, 256>>>(XL, 224, 200, Wt, 80, 64, t, 96, 0, 0, 0);
        for (int k = KH - 1; k >= 1; --k) {
            k_prop<3><<<WG, 256>>>(t, o);
            const float* Wk = Wl[3] + (size_t)k * 16000;
            k_gemm<4, 1><<<g1, 256>>>(XL, 224, 200, Wk, 80, 0,  o, 96, 0, 0, 0);
            k_gemm<1, 1><<<g1, 256>>>(XL, 224, 200, Wk, 80, 64, o, 96, 0, 0, 0);
            float* tmp = t; t = o; o = tmp;
        }
        k_prop<3><<<WG, 256>>>(t, o);
        k_gemm<4, 2><<<g1, 256>>>(XL, 224, 200, Wl[3], 80, 0,  o, 96, bl[3], AC, 96);
        k_gemm<1, 2><<<g1, 256>>>(XL, 224, 200, Wl[3], 80, 64, o, 96, bl[3], AC, 96);
    }

    // ---- layer 5: Cin=80 (X = AC stride 96), Cout=1 — fused Horner ----
    {
        float* tA = A0;
        float* tB = A1;
        k_l5<<<WG, 256>>>(AC, Wl[4] + (size_t)KH * 80, 0, tA, 1);
        const float* hold = tA;
        float* cur = tB;
        float* nxt = tA;
        for (int k = KH - 1; k >= 0; --k) {
            k_l5<<<WG, 256>>>(AC, Wl[4] + (size_t)k * 80, hold, cur, 0);
            hold = cur;
            float* tmp = cur; cur = nxt; nxt = tmp;
        }
        k_sigmoid<<<(NN + 255) / 256, 256>>>(hold, bl[4], out);
    }
}